// round 1
// baseline (speedup 1.0000x reference)
#include <cuda_runtime.h>
#include <cstdint>

// x: (131072, 28, 28) fp32. rows = 4 int32, cols = 4 int32.
// out[i,h,w] = mute(x) if (h in rows) || (w in cols) else x
// mute(x): if frexp-exponent e > 1 (i.e. |x| >= 2, biased exp >= 128),
//          replace exponent field with 126 -> |result| in [0.5, 1).
// mute is idempotent, so row-then-col order collapses to a single mask test.

static constexpr int HW = 28 * 28;      // 784, divisible by 4
static constexpr long long NELEM = 131072LL * HW;  // 102,760,448
static constexpr int N4 = (int)(NELEM / 4);        // 25,690,112 float4s

__device__ __forceinline__ float mute1(float x) {
    unsigned b = __float_as_uint(x);
    unsigned e = (b >> 23) & 0xFFu;
    // e in [128, 254] -> normal with frexp exponent > 1 (skip inf/nan at 255)
    if (e - 128u < 127u) {
        b = (b & 0x807FFFFFu) | (126u << 23);
    }
    return __uint_as_float(b);
}

__global__ void __launch_bounds__(256) mute_kernel(
    const float4* __restrict__ x,
    const int* __restrict__ rows,
    const int* __restrict__ cols,
    float4* __restrict__ out)
{
    int t = blockIdx.x * blockDim.x + threadIdx.x;
    if (t >= N4) return;

    // rows/cols are 4 ints each; broadcast loads, L1-resident after warmup.
    int r0 = rows[0], r1 = rows[1], r2 = rows[2], r3 = rows[3];
    int c0 = cols[0], c1 = cols[1], c2 = cols[2], c3 = cols[3];

    // position within the 28x28 image; float4 never crosses a row (4|28)
    int p = (t * 4) % HW;
    int h = p / 28;
    int w = p - h * 28;

    bool rmask = (h == r0) | (h == r1) | (h == r2) | (h == r3);

    float4 v = x[t];

    bool m0 = rmask | (w     == c0) | (w     == c1) | (w     == c2) | (w     == c3);
    bool m1 = rmask | (w + 1 == c0) | (w + 1 == c1) | (w + 1 == c2) | (w + 1 == c3);
    bool m2 = rmask | (w + 2 == c0) | (w + 2 == c1) | (w + 2 == c2) | (w + 2 == c3);
    bool m3 = rmask | (w + 3 == c0) | (w + 3 == c1) | (w + 3 == c2) | (w + 3 == c3);

    if (m0) v.x = mute1(v.x);
    if (m1) v.y = mute1(v.y);
    if (m2) v.z = mute1(v.z);
    if (m3) v.w = mute1(v.w);

    out[t] = v;
}

extern "C" void kernel_launch(void* const* d_in, const int* in_sizes, int n_in,
                              void* d_out, int out_size) {
    const float4* x   = (const float4*)d_in[0];
    const int* rows   = (const int*)d_in[1];
    const int* cols   = (const int*)d_in[2];
    float4* out       = (float4*)d_out;

    const int threads = 256;
    const int blocks  = (N4 + threads - 1) / threads;  // 100,352
    mute_kernel<<<blocks, threads>>>(x, rows, cols, out);
}

// round 2
// speedup vs baseline: 1.0182x; 1.0182x over previous
#include <cuda_runtime.h>
#include <cstdint>

// x: (131072, 28, 28) fp32. rows = 4 int32, cols = 4 int32.
// out[i,h,w] = mute(x) if (h in rows) || (w in cols) else x
// mute is idempotent -> row-then-col order collapses to single mask test.
// Mask depends only on (elem_index % 784), i.e. (float4_index % 196):
// build a 196-entry 4-bit-mask LUT in shared memory per block.

static constexpr int HW4 = 196;                     // float4 positions per image
static constexpr long long NELEM = 131072LL * 784;  // 102,760,448
static constexpr int N4 = (int)(NELEM / 4);         // 25,690,112 = 25088 * 1024
static constexpr int UNROLL = 4;
static constexpr int THREADS = 256;

__device__ __forceinline__ float mute1(float x) {
    unsigned b = __float_as_uint(x);
    unsigned e = (b >> 23) & 0xFFu;
    // biased exp in [128, 254] -> frexp exponent > 1 (exclude inf/nan = 255)
    if (e - 128u < 127u) {
        b = (b & 0x807FFFFFu) | (126u << 23);
    }
    return __uint_as_float(b);
}

__global__ void __launch_bounds__(THREADS) mute_kernel(
    const float4* __restrict__ x,
    const int* __restrict__ rows,
    const int* __restrict__ cols,
    float4* __restrict__ out)
{
    __shared__ unsigned char lut[HW4];

    int tid = threadIdx.x;
    if (tid < HW4) {
        int p = tid * 4;          // element offset within 28x28 image
        int h = p / 28;
        int w = p - h * 28;       // float4 never crosses a row (4 | 28)
        int r0 = rows[0], r1 = rows[1], r2 = rows[2], r3 = rows[3];
        int c0 = cols[0], c1 = cols[1], c2 = cols[2], c3 = cols[3];
        bool rm = (h == r0) | (h == r1) | (h == r2) | (h == r3);
        unsigned m = 0;
        #pragma unroll
        for (int k = 0; k < 4; k++) {
            bool cm = (w + k == c0) | (w + k == c1) | (w + k == c2) | (w + k == c3);
            if (rm | cm) m |= (1u << k);
        }
        lut[tid] = (unsigned char)m;
    }
    __syncthreads();

    int base = blockIdx.x * (THREADS * UNROLL) + tid;

    // Front-batch all 4 LDG.128s for MLP=4
    float4 v[UNROLL];
    #pragma unroll
    for (int k = 0; k < UNROLL; k++) {
        v[k] = x[base + k * THREADS];
    }

    #pragma unroll
    for (int k = 0; k < UNROLL; k++) {
        int idx = base + k * THREADS;
        unsigned m = lut[idx % HW4];
        if (m & 1u) v[k].x = mute1(v[k].x);
        if (m & 2u) v[k].y = mute1(v[k].y);
        if (m & 4u) v[k].z = mute1(v[k].z);
        if (m & 8u) v[k].w = mute1(v[k].w);
        out[idx] = v[k];
    }
}

extern "C" void kernel_launch(void* const* d_in, const int* in_sizes, int n_in,
                              void* d_out, int out_size) {
    const float4* x = (const float4*)d_in[0];
    const int* rows = (const int*)d_in[1];
    const int* cols = (const int*)d_in[2];
    float4* out     = (float4*)d_out;

    const int blocks = N4 / (THREADS * UNROLL);  // 25,088, exact
    mute_kernel<<<blocks, THREADS>>>(x, rows, cols, out);
}